// round 1
// baseline (speedup 1.0000x reference)
#include <cuda_runtime.h>
#include <stdint.h>

// Problem constants
#define B_   8
#define N_   8192
#define D_   512
#define P_   4
#define TOT  (B_ * N_ * D_)   // 33,554,432 floats = 128 MB

// Scratch: delta accumulator (128 MB). __device__ global to satisfy the
// no-allocation rules.
__device__ float g_delta[TOT];

// GEMM tile config
#define BM 128
#define BN 128
#define BK 16

// ---------------------------------------------------------------------------
// f32x2 packed-FMA helpers (Blackwell FFMA2 path: 2x fp32 FFMA throughput)
// ---------------------------------------------------------------------------
__device__ __forceinline__ void ffma2(unsigned long long& d,
                                      unsigned long long a,
                                      unsigned long long b) {
    asm volatile("fma.rn.f32x2 %0, %1, %2, %0;" : "+l"(d) : "l"(a), "l"(b));
}
__device__ __forceinline__ unsigned long long pack2_dup(float x) {
    unsigned long long r;
    asm("mov.b64 %0, {%1, %1};" : "=l"(r) : "f"(x));
    return r;
}
__device__ __forceinline__ float2 unpack2(unsigned long long v) {
    float2 f;
    asm("mov.b64 {%0, %1}, %2;" : "=f"(f.x), "=f"(f.y) : "l"(v));
    return f;
}
// Vector global reduction (sm_90+): 16B atomic add, no return.
__device__ __forceinline__ void red_add_v4(float* p, float a, float b,
                                           float c, float d) {
    asm volatile("red.global.add.v4.f32 [%0], {%1, %2, %3, %4};"
                 :: "l"(p), "f"(a), "f"(b), "f"(c), "f"(d) : "memory");
}

// ---------------------------------------------------------------------------
// init: upd = x, delta = 0   (d_out is poisoned, so full init required)
// ---------------------------------------------------------------------------
__global__ void init_kernel(const float* __restrict__ x, float* __restrict__ upd) {
    size_t i = ((size_t)blockIdx.x * blockDim.x + threadIdx.x) * 4;
    float4 v = *reinterpret_cast<const float4*>(x + i);
    *reinterpret_cast<float4*>(upd + i) = v;
    *reinterpret_cast<float4*>(g_delta + i) = make_float4(0.f, 0.f, 0.f, 0.f);
}

// ---------------------------------------------------------------------------
// update: upd += delta; delta = 0
// ---------------------------------------------------------------------------
__global__ void update_kernel(float* __restrict__ upd) {
    size_t i = ((size_t)blockIdx.x * blockDim.x + threadIdx.x) * 4;
    float4 u = *reinterpret_cast<float4*>(upd + i);
    float4 d = *reinterpret_cast<float4*>(g_delta + i);
    u.x += d.x; u.y += d.y; u.z += d.z; u.w += d.w;
    *reinterpret_cast<float4*>(upd + i) = u;
    *reinterpret_cast<float4*>(g_delta + i) = make_float4(0.f, 0.f, 0.f, 0.f);
}

// ---------------------------------------------------------------------------
// proj: for each (projection i, batch b), tile of the gathered GEMM
//   dx = scale * upd[b, groups[i, m], :] @ W[i]      (128x128 output tile)
//   delta[b, groups[i, m], :] += dx                  (vector atomics)
// grid: (D/BN=4, N/BM=64, B*P=32), 256 threads, 8x8 micro-tile per thread.
// ---------------------------------------------------------------------------
__global__ __launch_bounds__(256, 2)
void proj_kernel(const float* __restrict__ upd, const float* __restrict__ W,
                 const int* __restrict__ groups, float scale)
{
    __shared__ __align__(16) float As[BK][BM + 4];   // [k][m], +4 pad for banks
    __shared__ __align__(16) float Bs[BK][BN];       // [k][n]
    __shared__ int rowsrc[BM];

    const int tid  = threadIdx.x;
    const int bz   = blockIdx.z;
    const int proj = bz >> 3;        // 0..3
    const int b    = bz & 7;         // 0..7
    const int n0   = blockIdx.x * BN;
    const int m0   = blockIdx.y * BM;

    if (tid < BM) rowsrc[tid] = groups[proj * N_ + m0 + tid];
    __syncthreads();

    const float* Wp   = W + (size_t)proj * D_ * D_;
    const float* updb = upd + (size_t)b * N_ * D_;

    const int tx = tid & 15;   // n direction (8 cols each)
    const int ty = tid >> 4;   // m direction (8 rows each)

    // A-load mapping: tid%4 -> k-float4, tid/4 -> row (64 rows/pass, 2 passes)
    const int a_k4  = tid & 3;
    const int a_row = tid >> 2;
    // B-load mapping: tid%32 -> e-float4, tid/32 -> k row (8 rows/pass, 2 passes)
    const int b_e4  = tid & 31;
    const int b_kk  = tid >> 5;

    unsigned long long acc[8][4];
    #pragma unroll
    for (int i = 0; i < 8; i++)
        #pragma unroll
        for (int j = 0; j < 4; j++) acc[i][j] = 0ull;

    for (int k0 = 0; k0 < D_; k0 += BK) {
        __syncthreads();
        // Load A tile (gathered rows), store transposed As[k][m]
        #pragma unroll
        for (int p = 0; p < 2; p++) {
            int row = a_row + p * 64;
            int src = rowsrc[row];
            float4 v = *reinterpret_cast<const float4*>(
                updb + (size_t)src * D_ + k0 + a_k4 * 4);
            As[a_k4 * 4 + 0][row] = v.x;
            As[a_k4 * 4 + 1][row] = v.y;
            As[a_k4 * 4 + 2][row] = v.z;
            As[a_k4 * 4 + 3][row] = v.w;
        }
        // Load B tile (W is L2-resident, 1 MB per projection)
        #pragma unroll
        for (int p = 0; p < 2; p++) {
            int kk = b_kk + p * 8;
            *reinterpret_cast<float4*>(&Bs[kk][b_e4 * 4]) =
                *reinterpret_cast<const float4*>(
                    Wp + (size_t)(k0 + kk) * D_ + n0 + b_e4 * 4);
        }
        __syncthreads();

        #pragma unroll
        for (int kk = 0; kk < BK; kk++) {
            float4 a0 = *reinterpret_cast<const float4*>(&As[kk][ty * 8]);
            float4 a1 = *reinterpret_cast<const float4*>(&As[kk][ty * 8 + 4]);
            // b pairs read directly as 64-bit lanes (no repack needed)
            ulonglong2 bp01 = *reinterpret_cast<const ulonglong2*>(&Bs[kk][tx * 8]);
            ulonglong2 bp23 = *reinterpret_cast<const ulonglong2*>(&Bs[kk][tx * 8 + 4]);
            unsigned long long bp[4] = {bp01.x, bp01.y, bp23.x, bp23.y};
            float av[8] = {a0.x, a0.y, a0.z, a0.w, a1.x, a1.y, a1.z, a1.w};
            #pragma unroll
            for (int i = 0; i < 8; i++) {
                unsigned long long ap = pack2_dup(av[i]);
                #pragma unroll
                for (int j = 0; j < 4; j++) ffma2(acc[i][j], ap, bp[j]);
            }
        }
    }

    // Epilogue: scale + scatter-add (vector atomics, duplicates exist)
    #pragma unroll
    for (int i = 0; i < 8; i++) {
        int src = rowsrc[ty * 8 + i];
        float* drow = g_delta + ((size_t)b * N_ + src) * D_ + n0 + tx * 8;
        float2 c0 = unpack2(acc[i][0]);
        float2 c1 = unpack2(acc[i][1]);
        float2 c2 = unpack2(acc[i][2]);
        float2 c3 = unpack2(acc[i][3]);
        red_add_v4(drow,     c0.x * scale, c0.y * scale, c1.x * scale, c1.y * scale);
        red_add_v4(drow + 4, c2.x * scale, c2.y * scale, c3.x * scale, c3.y * scale);
    }
}

// ---------------------------------------------------------------------------
// kernel_launch
// ---------------------------------------------------------------------------
extern "C" void kernel_launch(void* const* d_in, const int* in_sizes, int n_in,
                              void* d_out, int out_size) {
    const float* x      = (const float*)d_in[0];
    const float* W      = (const float*)d_in[1];
    const int*   groups = (const int*)d_in[2];
    float*       upd    = (float*)d_out;

    const int vec_blocks = (TOT / 4) / 256;   // 32768 blocks of 256 thr, 1 float4 each
    init_kernel<<<vec_blocks, 256>>>(x, upd);

    dim3 grid(D_ / BN, N_ / BM, B_ * P_);     // (4, 64, 32)
    for (int ite = 0; ite < 3; ite++) {
        float scale = 1.0f / (float)(ite + 1);
        proj_kernel<<<grid, 256>>>(upd, W, groups, scale);
        update_kernel<<<vec_blocks, 256>>>(upd);
    }
}

// round 3
// speedup vs baseline: 2.1885x; 2.1885x over previous
#include <cuda_runtime.h>
#include <cuda_bf16.h>
#include <stdint.h>

// ---------------------------------------------------------------------------
// Problem: upd_{t+1} = upd_t + (1/(t+1)) * sum_i diag(cnt_i) upd_t W_i
// (gather/scatter with index list g is algebraically S^T S = diag(multiplicity))
// Cast as ONE dense GEMM per iteration:
//   C = A_stacked @ W_stacked,  M=65536, N=512, K=2048
//   A[m, i*512+k] = cnt_i[m%8192] * upd[m, k]   (built on the fly in the loader)
//   out[m, n] = in[m, n] + scale * C[m, n]      (fused epilogue, ping-pong bufs)
// Tensor path: mma.sync m16n8k16 bf16 (baseline PTX; tcgen05 unavailable on
// this toolchain's compute_103 target) with hi/lo split-bf16 (3 passes) for
// fp32-grade accuracy.
// ---------------------------------------------------------------------------

#define B_    8
#define N_    8192
#define D_    512
#define P_    4
#define MTOT  (B_ * N_)      // 65536
#define KTOT  (P_ * D_)      // 2048
#define TOT   (B_ * N_ * D_)

// Device scratch (no allocation allowed anywhere)
__device__ float          g_bufA[TOT];            // 128 MB ping
__device__ float          g_bufB[TOT];            // 128 MB pong
__device__ __nv_bfloat16  g_Wth[D_ * KTOT];       // W^T stacked hi: [n][kglobal]
__device__ __nv_bfloat16  g_Wtl[D_ * KTOT];       // W^T stacked lo
__device__ int            g_cnt[P_ * N_];         // multiplicity of row r in groups[i]

// ---------------------------------------------------------------------------
// helpers
// ---------------------------------------------------------------------------
__device__ __forceinline__ uint32_t smem_u32(const void* p) {
    uint32_t a;
    asm("{ .reg .u64 t; cvta.to.shared.u64 t, %1; cvt.u32.u64 %0, t; }"
        : "=r"(a) : "l"(p));
    return a;
}

__device__ __forceinline__ void ldsm4(uint32_t r[4], uint32_t addr) {
    asm volatile("ldmatrix.sync.aligned.m8n8.x4.shared.b16 {%0,%1,%2,%3}, [%4];"
                 : "=r"(r[0]), "=r"(r[1]), "=r"(r[2]), "=r"(r[3]) : "r"(addr));
}

__device__ __forceinline__ void mma16816(float c[4], const uint32_t a[4],
                                         uint32_t b0, uint32_t b1) {
    asm volatile(
        "mma.sync.aligned.m16n8k16.row.col.f32.bf16.bf16.f32 "
        "{%0,%1,%2,%3}, {%4,%5,%6,%7}, {%8,%9}, {%0,%1,%2,%3};"
        : "+f"(c[0]), "+f"(c[1]), "+f"(c[2]), "+f"(c[3])
        : "r"(a[0]), "r"(a[1]), "r"(a[2]), "r"(a[3]), "r"(b0), "r"(b1));
}

// pack two floats to bf16x2 (hi) and residual bf16x2 (lo); element order:
// f0 -> low halfword, f1 -> high halfword
__device__ __forceinline__ void split2(float f0, float f1,
                                       uint32_t& h, uint32_t& l) {
    uint32_t hh;
    asm("cvt.rn.bf16x2.f32 %0, %1, %2;" : "=r"(hh) : "f"(f1), "f"(f0));
    float h0 = __uint_as_float(hh << 16);
    float h1 = __uint_as_float(hh & 0xFFFF0000u);
    float l0 = f0 - h0, l1 = f1 - h1;
    asm("cvt.rn.bf16x2.f32 %0, %1, %2;" : "=r"(l) : "f"(l1), "f"(l0));
    h = hh;
}

// ---------------------------------------------------------------------------
// cnt kernels: zero, then histogram the group indices
// ---------------------------------------------------------------------------
__global__ void zero_cnt() {
    g_cnt[blockIdx.x * 256 + threadIdx.x] = 0;
}
__global__ void count_groups(const int* __restrict__ groups) {
    int idx = blockIdx.x * 256 + threadIdx.x;   // P*G*GS = 32768
    int i = idx >> 13;
    int r = groups[idx];
    atomicAdd(&g_cnt[i * N_ + r], 1);
}

// ---------------------------------------------------------------------------
// convert_Wt: W[i][k][n] fp32 -> g_Wth/g_Wtl [n][i*512+k] bf16 split
// grid (ntile=8, ktile=8, i=4), 256 threads
// ---------------------------------------------------------------------------
__global__ void convert_Wt(const float* __restrict__ W) {
    __shared__ float tile[64][65];
    const int nt = blockIdx.x * 64, kt = blockIdx.y * 64, i = blockIdx.z;
    const int tid = threadIdx.x;
    // load 64x64 (k-major rows), coalesced
    #pragma unroll
    for (int q = 0; q < 16; ++q) {
        int r = (tid >> 6) + q * 4;
        int c = tid & 63;
        tile[r][c] = W[(((size_t)i * D_) + kt + r) * D_ + nt + c];
    }
    __syncthreads();
    // write: row n, 16 consecutive k
    const int n  = tid >> 2;
    const int kp = tid & 3;
    uint32_t h[8], l[8];
    #pragma unroll
    for (int q = 0; q < 8; ++q)
        split2(tile[kp * 16 + 2 * q][n], tile[kp * 16 + 2 * q + 1][n], h[q], l[q]);
    size_t off = (size_t)(nt + n) * KTOT + i * D_ + kt + kp * 16;
    *reinterpret_cast<uint4*>(g_Wth + off)     = make_uint4(h[0], h[1], h[2], h[3]);
    *reinterpret_cast<uint4*>(g_Wth + off + 8) = make_uint4(h[4], h[5], h[6], h[7]);
    *reinterpret_cast<uint4*>(g_Wtl + off)     = make_uint4(l[0], l[1], l[2], l[3]);
    *reinterpret_cast<uint4*>(g_Wtl + off + 8) = make_uint4(l[4], l[5], l[6], l[7]);
}

// ---------------------------------------------------------------------------
// proj_mma: C[128m x 128n] tile of A_stacked @ W_stacked, fused epilogue
//   grid (4 n-tiles, 512 m-tiles), 256 threads = 8 warps (4m x 2n),
//   warp tile 32m x 64n, BK = 64 elems (one 128B smem row per tile row)
// ---------------------------------------------------------------------------
#define BKE     64
#define CHUNKS  (KTOT / BKE)        // 32
#define SM_A_HI 0
#define SM_A_LO 16384
#define SM_B_HI 32768
#define SM_B_LO 49152
#define SMEM_BYTES (65536 + 128)

__global__ __launch_bounds__(256, 2)
void proj_mma(const float* __restrict__ Ain, float* __restrict__ Cout,
              float scale)
{
    extern __shared__ char dyn_raw[];
    uint32_t raw = smem_u32(dyn_raw);
    uint32_t sm  = (raw + 127u) & ~127u;        // 128B align
    char*    smp = dyn_raw + (sm - raw);

    const int tid  = threadIdx.x;
    const int warp = tid >> 5, lane = tid & 31;
    const int n0   = blockIdx.x * 128;          // within D (=n of one W block)
    const int m0   = blockIdx.y * 128;
    const int wm   = (warp & 3) * 32;
    const int wn   = (warp >> 2) * 64;

    // loader mapping: 2 threads per A row (32 elems each); 2 per B row (32 elems)
    const int lrow  = tid >> 1;
    const int lpart = tid & 1;
    const int gm    = m0 + lrow;                // global m row
    const int rmod  = gm & (N_ - 1);            // row within batch (for cnt)
    const float* arow = Ain + (size_t)gm * D_;  // upd row (K=512 fp32)

    // ldmatrix per-thread addressing invariants
    const int jj = lane >> 3, ii = lane & 7;
    // A: block jj: (m + 8*(jj&1), k-half jj>>1)
    int aRowOff[2], aXor[2];
    #pragma unroll
    for (int mi = 0; mi < 2; ++mi) {
        int mrow = wm + mi * 16 + ii + ((jj & 1) << 3);
        aRowOff[mi] = mrow * 128;
        aXor[mi]    = mrow & 7;
    }
    const int aHalf = jj >> 1;
    // B: block jj: (n + 8*(jj>>1), k-half jj&1)
    int bRowOff[4], bXor[4];
    #pragma unroll
    for (int ni = 0; ni < 4; ++ni) {
        int nrow = wn + ni * 16 + ii + ((jj >> 1) << 3);
        bRowOff[ni] = nrow * 128;
        bXor[ni]    = nrow & 7;
    }
    const int bHalf = jj & 1;

    float acc[2][8][4];
    #pragma unroll
    for (int mi = 0; mi < 2; ++mi)
        #pragma unroll
        for (int ni = 0; ni < 8; ++ni)
            #pragma unroll
            for (int q = 0; q < 4; ++q) acc[mi][ni][q] = 0.f;

    for (int j = 0; j < CHUNKS; ++j) {
        const int i_blk = j >> 3;
        const int kk    = (j & 7) * BKE;
        __syncthreads();   // previous compute done before overwriting smem

        // ---- A: load 32 fp32, scale by cnt, split, store swizzled ----
        {
            float cnt = (float)g_cnt[i_blk * N_ + rmod];
            const float4* src = reinterpret_cast<const float4*>(arow + kk + lpart * 32);
            float v[32];
            #pragma unroll
            for (int q = 0; q < 8; ++q) {
                float4 t = src[q];
                v[q * 4 + 0] = t.x * cnt; v[q * 4 + 1] = t.y * cnt;
                v[q * 4 + 2] = t.z * cnt; v[q * 4 + 3] = t.w * cnt;
            }
            uint32_t h[16], l[16];
            #pragma unroll
            for (int q = 0; q < 16; ++q) split2(v[2 * q], v[2 * q + 1], h[q], l[q]);
            #pragma unroll
            for (int w = 0; w < 4; ++w) {
                int su = (lpart * 4 + w) ^ (lrow & 7);
                uint32_t off = lrow * 128 + su * 16;
                *reinterpret_cast<uint4*>(smp + SM_A_HI + off) =
                    make_uint4(h[4 * w], h[4 * w + 1], h[4 * w + 2], h[4 * w + 3]);
                *reinterpret_cast<uint4*>(smp + SM_A_LO + off) =
                    make_uint4(l[4 * w], l[4 * w + 1], l[4 * w + 2], l[4 * w + 3]);
            }
        }
        // ---- B: copy Wt hi/lo rows (bf16), store swizzled ----
        {
            size_t off = (size_t)(n0 + lrow) * KTOT + j * BKE + lpart * 32;
            const uint4* sh = reinterpret_cast<const uint4*>(g_Wth + off);
            const uint4* sl = reinterpret_cast<const uint4*>(g_Wtl + off);
            #pragma unroll
            for (int w = 0; w < 4; ++w) {
                int su = (lpart * 4 + w) ^ (lrow & 7);
                uint32_t o = lrow * 128 + su * 16;
                *reinterpret_cast<uint4*>(smp + SM_B_HI + o) = sh[w];
                *reinterpret_cast<uint4*>(smp + SM_B_LO + o) = sl[w];
            }
        }
        __syncthreads();

        // ---- compute: 4 k16 steps, 3 split passes ----
        #pragma unroll
        for (int k2 = 0; k2 < 4; ++k2) {
            uint32_t ah[2][4], al[2][4];
            #pragma unroll
            for (int mi = 0; mi < 2; ++mi) {
                uint32_t ua = ((k2 * 2 + aHalf) ^ aXor[mi]) * 16 + aRowOff[mi];
                ldsm4(ah[mi], sm + SM_A_HI + ua);
                ldsm4(al[mi], sm + SM_A_LO + ua);
            }
            #pragma unroll
            for (int ni = 0; ni < 4; ++ni) {
                uint32_t ub = ((k2 * 2 + bHalf) ^ bXor[ni]) * 16 + bRowOff[ni];
                uint32_t bh[4], bl[4];
                ldsm4(bh, sm + SM_B_HI + ub);
                ldsm4(bl, sm + SM_B_LO + ub);
                #pragma unroll
                for (int mi = 0; mi < 2; ++mi) {
                    mma16816(acc[mi][2 * ni],     ah[mi], bh[0], bh[1]);
                    mma16816(acc[mi][2 * ni + 1], ah[mi], bh[2], bh[3]);
                    mma16816(acc[mi][2 * ni],     al[mi], bh[0], bh[1]);
                    mma16816(acc[mi][2 * ni + 1], al[mi], bh[2], bh[3]);
                    mma16816(acc[mi][2 * ni],     ah[mi], bl[0], bl[1]);
                    mma16816(acc[mi][2 * ni + 1], ah[mi], bl[2], bl[3]);
                }
            }
        }
    }

    // ---- fused epilogue: out = in + scale * acc (each element exactly once)
    #pragma unroll
    for (int mi = 0; mi < 2; ++mi) {
        int row = m0 + wm + mi * 16 + (lane >> 2);
        #pragma unroll
        for (int ni = 0; ni < 8; ++ni) {
            int col = n0 + wn + ni * 8 + (lane & 3) * 2;
            size_t o0 = (size_t)row * D_ + col;
            size_t o1 = o0 + 8 * D_;
            float2 i0 = *reinterpret_cast<const float2*>(Ain + o0);
            float2 i1 = *reinterpret_cast<const float2*>(Ain + o1);
            float2 r0 = make_float2(i0.x + scale * acc[mi][ni][0],
                                    i0.y + scale * acc[mi][ni][1]);
            float2 r1 = make_float2(i1.x + scale * acc[mi][ni][2],
                                    i1.y + scale * acc[mi][ni][3]);
            *reinterpret_cast<float2*>(Cout + o0) = r0;
            *reinterpret_cast<float2*>(Cout + o1) = r1;
        }
    }
}

// ---------------------------------------------------------------------------
// kernel_launch
// ---------------------------------------------------------------------------
extern "C" void kernel_launch(void* const* d_in, const int* in_sizes, int n_in,
                              void* d_out, int out_size) {
    const float* x      = (const float*)d_in[0];
    const float* W      = (const float*)d_in[1];
    const int*   groups = (const int*)d_in[2];
    float*       out    = (float*)d_out;

    cudaFuncSetAttribute(proj_mma, cudaFuncAttributeMaxDynamicSharedMemorySize,
                         SMEM_BYTES);

    zero_cnt<<<(P_ * N_) / 256, 256>>>();
    count_groups<<<(P_ * N_) / 256, 256>>>(groups);   // P*G*GS == P*N here
    convert_Wt<<<dim3(8, 8, 4), 256>>>(W);

    float *bufA, *bufB;
    cudaGetSymbolAddress((void**)&bufA, g_bufA);
    cudaGetSymbolAddress((void**)&bufB, g_bufB);

    dim3 grid(4, 512);
    // it0: x -> bufA; it1: bufA -> bufB; it2: bufB -> d_out
    proj_mma<<<grid, 256, SMEM_BYTES>>>(x,    bufA, 1.0f);
    proj_mma<<<grid, 256, SMEM_BYTES>>>(bufA, bufB, 0.5f);
    proj_mma<<<grid, 256, SMEM_BYTES>>>(bufB, out,  1.0f / 3.0f);
}

// round 4
// speedup vs baseline: 3.7952x; 1.7342x over previous
#include <cuda_runtime.h>
#include <cuda_fp16.h>
#include <stdint.h>

// ---------------------------------------------------------------------------
// upd_{t+1} = upd_t + (1/(t+1)) * sum_i diag(cnt_i) upd_t W_i
// One dense GEMM per iteration: M=65536, N=512, K=2048
//   A[m, i*512+k] = cnt_i[m%8192] * upd[m,k]   (built in the loader, fp16)
//   W stacked, fp16 hi/lo split, pre-baked in mma-FRAGMENT layout in global.
// 2-pass split: C = A_f16 @ (Wh + Wl). Only A's fp16 rounding (2^-12) remains.
// ---------------------------------------------------------------------------

#define B_    8
#define N_    8192
#define D_    512
#define P_    4
#define KTOT  (P_ * D_)      // 2048
#define TOT   (B_ * N_ * D_)

// Device scratch
__device__ float g_bufA[TOT];                       // ping
__device__ float g_bufB[TOT];                       // pong
__device__ uint4 g_Wfrag[P_ * 32 * 64 * 32];        // fragment-layout W (4 MB)
__device__ int   g_cnt[P_ * N_];

// ---------------------------------------------------------------------------
// helpers
// ---------------------------------------------------------------------------
__device__ __forceinline__ uint32_t smem_u32(const void* p) {
    uint32_t a;
    asm("{ .reg .u64 t; cvta.to.shared.u64 t, %1; cvt.u32.u64 %0, t; }"
        : "=r"(a) : "l"(p));
    return a;
}

__device__ __forceinline__ void ldsm4(uint32_t r[4], uint32_t addr) {
    asm volatile("ldmatrix.sync.aligned.m8n8.x4.shared.b16 {%0,%1,%2,%3}, [%4];"
                 : "=r"(r[0]), "=r"(r[1]), "=r"(r[2]), "=r"(r[3]) : "r"(addr));
}

__device__ __forceinline__ void mma16816(float c[4], const uint32_t a[4],
                                         uint32_t b0, uint32_t b1) {
    asm volatile(
        "mma.sync.aligned.m16n8k16.row.col.f32.f16.f16.f32 "
        "{%0,%1,%2,%3}, {%4,%5,%6,%7}, {%8,%9}, {%0,%1,%2,%3};"
        : "+f"(c[0]), "+f"(c[1]), "+f"(c[2]), "+f"(c[3])
        : "r"(a[0]), "r"(a[1]), "r"(a[2]), "r"(a[3]), "r"(b0), "r"(b1));
}

__device__ __forceinline__ uint32_t pack_h2(float a, float b) {
    __half2 h = __float22half2_rn(make_float2(a, b));  // a -> low halfword
    return *reinterpret_cast<uint32_t*>(&h);
}

// ---------------------------------------------------------------------------
// cnt histogram
// ---------------------------------------------------------------------------
__global__ void zero_cnt() { g_cnt[blockIdx.x * 256 + threadIdx.x] = 0; }
__global__ void count_groups(const int* __restrict__ groups) {
    int idx = blockIdx.x * 256 + threadIdx.x;   // P*G*GS = 32768
    atomicAdd(&g_cnt[(idx >> 13) * N_ + groups[idx]], 1);
}

// ---------------------------------------------------------------------------
// convert_Wfrag: W[i][k][n] fp32 -> per-lane mma B fragments, fp16 hi/lo.
// For m16n8k16 .row.col: lane L holds b0 = B[k0, n], B[k0+1, n];
// b1 = B[k0+8, n], B[k0+9, n]; with k0 = s*16 + (L&3)*2, n = nb*8 + (L>>2).
// uint4 = {bh0, bh1, bl0, bl1}. Index = ((i*32+s)*64 + nb)*32 + lane.
// ---------------------------------------------------------------------------
__global__ void convert_Wfrag(const float* __restrict__ W) {
    int t = blockIdx.x * 256 + threadIdx.x;     // 0..262143
    int lane = t & 31, nbg = (t >> 5) & 63, s = (t >> 11) & 31, i = t >> 16;
    int k0 = s * 16 + (lane & 3) * 2;
    int n  = nbg * 8 + (lane >> 2);
    const float* Wp = W + (size_t)i * D_ * D_;
    float w00 = Wp[(size_t)(k0    ) * D_ + n];
    float w01 = Wp[(size_t)(k0 + 1) * D_ + n];
    float w10 = Wp[(size_t)(k0 + 8) * D_ + n];
    float w11 = Wp[(size_t)(k0 + 9) * D_ + n];
    float h00 = __half2float(__float2half_rn(w00));
    float h01 = __half2float(__float2half_rn(w01));
    float h10 = __half2float(__float2half_rn(w10));
    float h11 = __half2float(__float2half_rn(w11));
    uint4 b;
    b.x = pack_h2(h00, h01);
    b.y = pack_h2(h10, h11);
    b.z = pack_h2(w00 - h00, w01 - h01);
    b.w = pack_h2(w10 - h10, w11 - h11);
    g_Wfrag[t] = b;
}

// ---------------------------------------------------------------------------
// proj_mma: CTA 128m x 128n, 4 warps (2x2), warp tile 64x64.
//   A: fp32 global -> cnt-scale -> fp16 -> 16KB smem (swizzled) -> ldmatrix
//   B: direct LDG.128 of pre-baked fragments (no smem)
//   2 passes per fragment pair: A*Wh + A*Wl
//   epilogue: out = in + scale * acc
// ---------------------------------------------------------------------------
__global__ __launch_bounds__(128, 2)
void proj_mma(const float* __restrict__ Ain, float* __restrict__ Cout,
              float scale)
{
    __shared__ __align__(128) uint4 sA[128 * 8];   // 128 rows x 128B (fp16 x64)

    const int tid  = threadIdx.x;
    const int warp = tid >> 5, lane = tid & 31;
    const int n0   = blockIdx.x * 128;
    const int m0   = blockIdx.y * 128;
    const int wm   = (warp >> 1) * 64;
    const int wn   = (warp & 1) * 64;

    const uint32_t sA32 = smem_u32(sA);

    // ldmatrix addressing for A (4 mi blocks of m16 x k16)
    const int jj = lane >> 3, ii = lane & 7;
    int aRow[4], aXor[4];
    #pragma unroll
    for (int mi = 0; mi < 4; ++mi) {
        int r = wm + mi * 16 + ii + ((jj & 1) << 3);
        aRow[mi] = r * 128;
        aXor[mi] = r & 7;
    }
    const int aHalf = jj >> 1;

    // loader mapping: 4 threads per row (16 floats each), 4 row passes
    const int lpart = tid & 3;
    const int lrow4 = tid >> 2;

    float acc[4][8][4];
    #pragma unroll
    for (int mi = 0; mi < 4; ++mi)
        #pragma unroll
        for (int nb = 0; nb < 8; ++nb)
            #pragma unroll
            for (int q = 0; q < 4; ++q) acc[mi][nb][q] = 0.f;

    const int nbg0 = blockIdx.x * 16 + (warp & 1) * 8;

    for (int j = 0; j < 32; ++j) {
        const int i_blk = j >> 3;
        const int kk    = (j & 7) * 64;
        __syncthreads();

        // ---- load A chunk: fp32 -> cnt scale -> fp16, swizzled ----
        #pragma unroll
        for (int p = 0; p < 4; ++p) {
            int row = lrow4 + p * 32;
            int gm  = m0 + row;
            float cnt = (float)g_cnt[i_blk * N_ + (gm & (N_ - 1))];
            const float4* src = reinterpret_cast<const float4*>(
                Ain + (size_t)gm * D_ + kk + lpart * 16);
            uint32_t h[8];
            #pragma unroll
            for (int q = 0; q < 4; ++q) {
                float4 f = src[q];
                h[2 * q]     = pack_h2(f.x * cnt, f.y * cnt);
                h[2 * q + 1] = pack_h2(f.z * cnt, f.w * cnt);
            }
            int u0 = (lpart * 2)     ^ (row & 7);
            int u1 = (lpart * 2 + 1) ^ (row & 7);
            sA[row * 8 + u0] = make_uint4(h[0], h[1], h[2], h[3]);
            sA[row * 8 + u1] = make_uint4(h[4], h[5], h[6], h[7]);
        }
        __syncthreads();

        // ---- compute: 4 k16 steps ----
        const uint4* wf = g_Wfrag +
            ((size_t)(i_blk * 32 + (j & 7) * 4) * 64 + nbg0) * 32 + lane;
        #pragma unroll
        for (int k2 = 0; k2 < 4; ++k2) {
            uint32_t a[4][4];
            #pragma unroll
            for (int mi = 0; mi < 4; ++mi) {
                uint32_t u = ((k2 * 2 + aHalf) ^ aXor[mi]);
                ldsm4(a[mi], sA32 + aRow[mi] + u * 16);
            }
            const uint4* wk = wf + (size_t)k2 * 64 * 32;
            #pragma unroll
            for (int nb = 0; nb < 8; ++nb) {
                uint4 b = wk[(size_t)nb * 32];
                #pragma unroll
                for (int mi = 0; mi < 4; ++mi) {
                    mma16816(acc[mi][nb], a[mi], b.x, b.y);   // A * W_hi
                    mma16816(acc[mi][nb], a[mi], b.z, b.w);   // A * W_lo
                }
            }
        }
    }

    // ---- fused epilogue: out = in + scale * acc ----
    #pragma unroll
    for (int mi = 0; mi < 4; ++mi) {
        int row = m0 + wm + mi * 16 + (lane >> 2);
        #pragma unroll
        for (int nb = 0; nb < 8; ++nb) {
            int col = n0 + wn + nb * 8 + (lane & 3) * 2;
            size_t o0 = (size_t)row * D_ + col;
            size_t o1 = o0 + 8 * D_;
            float2 i0 = *reinterpret_cast<const float2*>(Ain + o0);
            float2 i1 = *reinterpret_cast<const float2*>(Ain + o1);
            float2 r0 = make_float2(i0.x + scale * acc[mi][nb][0],
                                    i0.y + scale * acc[mi][nb][1]);
            float2 r1 = make_float2(i1.x + scale * acc[mi][nb][2],
                                    i1.y + scale * acc[mi][nb][3]);
            *reinterpret_cast<float2*>(Cout + o0) = r0;
            *reinterpret_cast<float2*>(Cout + o1) = r1;
        }
    }
}

// ---------------------------------------------------------------------------
// kernel_launch
// ---------------------------------------------------------------------------
extern "C" void kernel_launch(void* const* d_in, const int* in_sizes, int n_in,
                              void* d_out, int out_size) {
    const float* x      = (const float*)d_in[0];
    const float* W      = (const float*)d_in[1];
    const int*   groups = (const int*)d_in[2];
    float*       out    = (float*)d_out;

    zero_cnt<<<(P_ * N_) / 256, 256>>>();
    count_groups<<<(P_ * N_) / 256, 256>>>(groups);
    convert_Wfrag<<<(P_ * 32 * 64 * 32) / 256, 256>>>(W);

    float *bufA, *bufB;
    cudaGetSymbolAddress((void**)&bufA, g_bufA);
    cudaGetSymbolAddress((void**)&bufB, g_bufB);

    dim3 grid(4, 512);
    proj_mma<<<grid, 128>>>(x,    bufA, 1.0f);
    proj_mma<<<grid, 128>>>(bufA, bufB, 0.5f);
    proj_mma<<<grid, 128>>>(bufB, out,  1.0f / 3.0f);
}

// round 5
// speedup vs baseline: 5.0594x; 1.3331x over previous
#include <cuda_runtime.h>
#include <cuda_fp16.h>
#include <stdint.h>

// ---------------------------------------------------------------------------
// upd_{t+1} = upd_t + (1/(t+1)) * sum_i diag(cnt_i) upd_t W_i
// One dense GEMM per iteration: M=65536, N=512, K=2048
//   A[m, i*512+k] = cnt_i[m%8192] * upd[m,k]   (built in the loader, fp16)
//   W stacked, fp16, pre-baked in mma-fragment layout (uint2 per lane, 2 MB).
// Single-pass fp16 (A and W both fp16-rounded): measured-error budget says
// ~2.6e-4 total vs the 1e-3 gate.
// ---------------------------------------------------------------------------

#define B_    8
#define N_    8192
#define D_    512
#define P_    4
#define KTOT  (P_ * D_)      // 2048
#define TOT   (B_ * N_ * D_)

// Device scratch
__device__ float g_bufA[TOT];                      // ping
__device__ float g_bufB[TOT];                      // pong
__device__ uint2 g_Wfrag2[P_ * 32 * 64 * 32];      // fragment-layout W hi (2 MB)
__device__ int   g_cnt[P_ * N_];

// ---------------------------------------------------------------------------
// helpers
// ---------------------------------------------------------------------------
__device__ __forceinline__ uint32_t smem_u32(const void* p) {
    uint32_t a;
    asm("{ .reg .u64 t; cvta.to.shared.u64 t, %1; cvt.u32.u64 %0, t; }"
        : "=r"(a) : "l"(p));
    return a;
}

__device__ __forceinline__ void ldsm4(uint32_t r[4], uint32_t addr) {
    asm volatile("ldmatrix.sync.aligned.m8n8.x4.shared.b16 {%0,%1,%2,%3}, [%4];"
                 : "=r"(r[0]), "=r"(r[1]), "=r"(r[2]), "=r"(r[3]) : "r"(addr));
}

__device__ __forceinline__ void mma16816(float c[4], const uint32_t a[4],
                                         uint32_t b0, uint32_t b1) {
    asm volatile(
        "mma.sync.aligned.m16n8k16.row.col.f32.f16.f16.f32 "
        "{%0,%1,%2,%3}, {%4,%5,%6,%7}, {%8,%9}, {%0,%1,%2,%3};"
        : "+f"(c[0]), "+f"(c[1]), "+f"(c[2]), "+f"(c[3])
        : "r"(a[0]), "r"(a[1]), "r"(a[2]), "r"(a[3]), "r"(b0), "r"(b1));
}

__device__ __forceinline__ uint32_t pack_h2(float a, float b) {
    __half2 h = __float22half2_rn(make_float2(a, b));  // a -> low halfword
    return *reinterpret_cast<uint32_t*>(&h);
}

// ---------------------------------------------------------------------------
// cnt histogram
// ---------------------------------------------------------------------------
__global__ void zero_cnt() { g_cnt[blockIdx.x * 256 + threadIdx.x] = 0; }
__global__ void count_groups(const int* __restrict__ groups) {
    int idx = blockIdx.x * 256 + threadIdx.x;   // P*G*GS = 32768
    atomicAdd(&g_cnt[(idx >> 13) * N_ + groups[idx]], 1);
}

// ---------------------------------------------------------------------------
// convert_Wfrag: W[i][k][n] fp32 -> per-lane mma B fragments (fp16).
// m16n8k16 .row.col: lane L holds b0 = B[k0, n], B[k0+1, n];
// b1 = B[k0+8, n], B[k0+9, n]; k0 = s*16 + (L&3)*2, n = nb*8 + (L>>2).
// Index = ((i*32+s)*64 + nb)*32 + lane.
// ---------------------------------------------------------------------------
__global__ void convert_Wfrag(const float* __restrict__ W) {
    int t = blockIdx.x * 256 + threadIdx.x;     // 0..262143
    int lane = t & 31, nbg = (t >> 5) & 63, s = (t >> 11) & 31, i = t >> 16;
    int k0 = s * 16 + (lane & 3) * 2;
    int n  = nbg * 8 + (lane >> 2);
    const float* Wp = W + (size_t)i * D_ * D_;
    uint2 b;
    b.x = pack_h2(Wp[(size_t)(k0    ) * D_ + n], Wp[(size_t)(k0 + 1) * D_ + n]);
    b.y = pack_h2(Wp[(size_t)(k0 + 8) * D_ + n], Wp[(size_t)(k0 + 9) * D_ + n]);
    g_Wfrag2[t] = b;
}

// ---------------------------------------------------------------------------
// proj_mma: CTA 128m x 128n, 4 warps (2x2), warp tile 64x64, fp16 single pass.
//   A: fp32 global -> cnt-scale -> fp16 -> double-buffered smem (swizzled)
//      loader pipelined against compute (LDG before MMA block, STS after)
//   B: LDG of pre-baked fragments, prefetched one k2-step ahead
//   epilogue: out = in + scale * acc
// ---------------------------------------------------------------------------
__global__ __launch_bounds__(128, 2)
void proj_mma(const float* __restrict__ Ain, float* __restrict__ Cout,
              float scale)
{
    __shared__ __align__(128) uint4 sA[2][128 * 8];   // 2 x 16 KB

    const int tid  = threadIdx.x;
    const int warp = tid >> 5, lane = tid & 31;
    const int n0   = blockIdx.x * 128;
    const int m0   = blockIdx.y * 128;
    const int wm   = (warp >> 1) * 64;
    const int wn   = (warp & 1) * 64;

    uint32_t sB32[2] = { smem_u32(&sA[0][0]), smem_u32(&sA[1][0]) };

    // ldmatrix addressing for A (4 mi blocks of m16 x k16)
    const int jj = lane >> 3, ii = lane & 7;
    int aRow[4], aXor[4];
    #pragma unroll
    for (int mi = 0; mi < 4; ++mi) {
        int r = wm + mi * 16 + ii + ((jj & 1) << 3);
        aRow[mi] = r * 128;
        aXor[mi] = r & 7;
    }
    const int aHalf = jj >> 1;

    // loader mapping: 4 threads per row (16 floats), pass p covers rows p*32..
    const int lpart = tid & 3;
    const int lrow4 = tid >> 2;
    const int rmod  = (m0 + lrow4) & (N_ - 1);

    float acc[4][8][4];
    #pragma unroll
    for (int mi = 0; mi < 4; ++mi)
        #pragma unroll
        for (int nb = 0; nb < 8; ++nb)
            #pragma unroll
            for (int q = 0; q < 4; ++q) acc[mi][nb][q] = 0.f;

    const int nbg0 = blockIdx.x * 16 + (warp & 1) * 8;

    // ---- loader pieces ----
    auto lda = [&](int j, int p, float4 st[4]) {
        const int kk = (j & 7) * 64;
        int row = lrow4 + p * 32;
        const float4* src = reinterpret_cast<const float4*>(
            Ain + (size_t)(m0 + row) * D_ + kk + lpart * 16);
        #pragma unroll
        for (int q = 0; q < 4; ++q) st[q] = src[q];
    };
    auto sta = [&](int j, int p, int buf, const float4 st[4]) {
        int row = lrow4 + p * 32;
        float cnt = (float)g_cnt[(j >> 3) * N_ + ((rmod + p * 32) & (N_ - 1))];
        uint32_t h[8];
        #pragma unroll
        for (int q = 0; q < 4; ++q) {
            h[2 * q]     = pack_h2(st[q].x * cnt, st[q].y * cnt);
            h[2 * q + 1] = pack_h2(st[q].z * cnt, st[q].w * cnt);
        }
        int u0 = (lpart * 2)     ^ (row & 7);
        int u1 = (lpart * 2 + 1) ^ (row & 7);
        sA[buf][row * 8 + u0] = make_uint4(h[0], h[1], h[2], h[3]);
        sA[buf][row * 8 + u1] = make_uint4(h[4], h[5], h[6], h[7]);
    };

    // ---- prologue: chunk 0 into buffer 0 ----
    #pragma unroll
    for (int p = 0; p < 4; ++p) {
        float4 st[4];
        lda(0, p, st);
        sta(0, p, 0, st);
    }
    __syncthreads();

    // ---- mainloop ----
    for (int j = 0; j < 32; ++j) {
        const int cur  = j & 1;
        const bool more = (j + 1 < 32);
        const uint2* wb = g_Wfrag2 +
            ((size_t)((j >> 3) * 32 + (j & 7) * 4) * 64 + nbg0) * 32 + lane;

        // B prefetch for k2 = 0
        uint2 bcur[8];
        #pragma unroll
        for (int nb = 0; nb < 8; ++nb) bcur[nb] = wb[(size_t)nb * 32];

        #pragma unroll
        for (int k2 = 0; k2 < 4; ++k2) {
            // stage A LDG for pass k2 of chunk j+1 (latency hidden by MMAs)
            float4 st[4];
            if (more) lda(j + 1, k2, st);

            // A fragments for this k-step
            uint32_t a[4][4];
            #pragma unroll
            for (int mi = 0; mi < 4; ++mi) {
                uint32_t u = ((k2 * 2 + aHalf) ^ aXor[mi]);
                ldsm4(a[mi], sB32[cur] + aRow[mi] + u * 16);
            }

            // B prefetch for next k-step
            uint2 bnext[8];
            if (k2 < 3) {
                const uint2* wk = wb + (size_t)(k2 + 1) * 64 * 32;
                #pragma unroll
                for (int nb = 0; nb < 8; ++nb) bnext[nb] = wk[(size_t)nb * 32];
            }

            #pragma unroll
            for (int nb = 0; nb < 8; ++nb)
                #pragma unroll
                for (int mi = 0; mi < 4; ++mi)
                    mma16816(acc[mi][nb], a[mi], bcur[nb].x, bcur[nb].y);

            // commit staged A into the other buffer
            if (more) sta(j + 1, k2, cur ^ 1, st);

            #pragma unroll
            for (int nb = 0; nb < 8; ++nb) bcur[nb] = bnext[nb];
        }
        __syncthreads();
    }

    // ---- fused epilogue: out = in + scale * acc ----
    #pragma unroll
    for (int mi = 0; mi < 4; ++mi) {
        int row = m0 + wm + mi * 16 + (lane >> 2);
        #pragma unroll
        for (int nb = 0; nb < 8; ++nb) {
            int col = n0 + wn + nb * 8 + (lane & 3) * 2;
            size_t o0 = (size_t)row * D_ + col;
            size_t o1 = o0 + 8 * D_;
            float2 i0 = *reinterpret_cast<const float2*>(Ain + o0);
            float2 i1 = *reinterpret_cast<const float2*>(Ain + o1);
            float2 r0 = make_float2(i0.x + scale * acc[mi][nb][0],
                                    i0.y + scale * acc[mi][nb][1]);
            float2 r1 = make_float2(i1.x + scale * acc[mi][nb][2],
                                    i1.y + scale * acc[mi][nb][3]);
            *reinterpret_cast<float2*>(Cout + o0) = r0;
            *reinterpret_cast<float2*>(Cout + o1) = r1;
        }
    }
}

// ---------------------------------------------------------------------------
// kernel_launch
// ---------------------------------------------------------------------------
extern "C" void kernel_launch(void* const* d_in, const int* in_sizes, int n_in,
                              void* d_out, int out_size) {
    const float* x      = (const float*)d_in[0];
    const float* W      = (const float*)d_in[1];
    const int*   groups = (const int*)d_in[2];
    float*       out    = (float*)d_out;

    zero_cnt<<<(P_ * N_) / 256, 256>>>();
    count_groups<<<(P_ * N_) / 256, 256>>>(groups);
    convert_Wfrag<<<(P_ * 32 * 64 * 32) / 256, 256>>>(W);

    float *bufA, *bufB;
    cudaGetSymbolAddress((void**)&bufA, g_bufA);
    cudaGetSymbolAddress((void**)&bufB, g_bufB);

    dim3 grid(4, 512);
    proj_mma<<<grid, 128>>>(x,    bufA, 1.0f);
    proj_mma<<<grid, 128>>>(bufA, bufB, 0.5f);
    proj_mma<<<grid, 128>>>(bufB, out,  1.0f / 3.0f);
}

// round 6
// speedup vs baseline: 8.4237x; 1.6650x over previous
#include <cuda_runtime.h>
#include <cuda_fp16.h>
#include <stdint.h>

// ---------------------------------------------------------------------------
// upd_{t+1} = upd_t + (1/(t+1)) * sum_i diag(cnt_i) upd_t W_i
// Dense GEMM per iteration: M=65536, N=512, K=2048 (4 stacked W blocks).
// Everything in mma-FRAGMENT layout in global memory:
//   - W  : fp16 fragments (uint2/lane), built once              (2 MB)
//   - A  : fp16 fragments (uint4/lane) of upd, UNscaled         (64 MB x2)
//          cnt_i folded in at runtime via mul.f16x2 (exact small int)
//   - A fragments for iter t+1 are emitted by iter t's epilogue (fused).
// No shared memory, no ldmatrix, no __syncthreads in the GEMM.
// ---------------------------------------------------------------------------

#define B_    8
#define N_    8192
#define D_    512
#define P_    4
#define MTOT  (B_ * N_)          // 65536
#define TOT   (B_ * N_ * D_)
#define MBLK  (MTOT / 16)        // 4096
#define KSTEP (D_ / 16)          // 32

// Device scratch
__device__ float g_bufA[TOT];                       // fp32 state ping
__device__ float g_bufB[TOT];                       // fp32 state pong
__device__ uint4 g_Afrag[2][(size_t)MBLK * KSTEP * 32];  // 2 x 64 MB
__device__ uint2 g_Wfrag2[P_ * KSTEP * 64 * 32];    // 2 MB
__device__ int   g_cnt[P_ * N_];

// ---------------------------------------------------------------------------
// helpers
// ---------------------------------------------------------------------------
__device__ __forceinline__ void mma16816(float c[4], const uint32_t a[4],
                                         uint32_t b0, uint32_t b1) {
    asm volatile(
        "mma.sync.aligned.m16n8k16.row.col.f32.f16.f16.f32 "
        "{%0,%1,%2,%3}, {%4,%5,%6,%7}, {%8,%9}, {%0,%1,%2,%3};"
        : "+f"(c[0]), "+f"(c[1]), "+f"(c[2]), "+f"(c[3])
        : "r"(a[0]), "r"(a[1]), "r"(a[2]), "r"(a[3]), "r"(b0), "r"(b1));
}

__device__ __forceinline__ uint32_t pack_h2(float a, float b) {
    __half2 h = __float22half2_rn(make_float2(a, b));  // a -> low halfword
    return *reinterpret_cast<uint32_t*>(&h);
}

__device__ __forceinline__ uint32_t hmul2(uint32_t a, uint32_t c) {
    uint32_t r;
    asm("mul.rn.f16x2 %0, %1, %2;" : "=r"(r) : "r"(a), "r"(c));
    return r;
}

// ---------------------------------------------------------------------------
// cnt histogram
// ---------------------------------------------------------------------------
__global__ void zero_cnt() { g_cnt[blockIdx.x * 256 + threadIdx.x] = 0; }
__global__ void count_groups(const int* __restrict__ groups) {
    int idx = blockIdx.x * 256 + threadIdx.x;   // P*G*GS = 32768
    atomicAdd(&g_cnt[(idx >> 13) * N_ + groups[idx]], 1);
}

// ---------------------------------------------------------------------------
// convert_Wfrag: W[i][k][n] fp32 -> per-lane mma B fragments (fp16).
// lane L: b0 = {B[k0,n], B[k0+1,n]}, b1 = {B[k0+8,n], B[k0+9,n]},
// k0 = s*16 + (L&3)*2, n = nb*8 + (L>>2). Index = ((i*32+s)*64 + nb)*32 + L.
// ---------------------------------------------------------------------------
__global__ void convert_Wfrag(const float* __restrict__ W) {
    int t = blockIdx.x * 256 + threadIdx.x;     // 0..262143
    int lane = t & 31, nbg = (t >> 5) & 63, s = (t >> 11) & 31, i = t >> 16;
    int k0 = s * 16 + (lane & 3) * 2;
    int n  = nbg * 8 + (lane >> 2);
    const float* Wp = W + (size_t)i * D_ * D_;
    uint2 b;
    b.x = pack_h2(Wp[(size_t)(k0    ) * D_ + n], Wp[(size_t)(k0 + 1) * D_ + n]);
    b.y = pack_h2(Wp[(size_t)(k0 + 8) * D_ + n], Wp[(size_t)(k0 + 9) * D_ + n]);
    g_Wfrag2[t] = b;
}

// ---------------------------------------------------------------------------
// convert_Afrag: fp32 matrix [MTOT x D] -> fp16 A fragments.
// lane L of (m_blk, kstep): r = m_blk*16 + (L>>2), k0 = kstep*16 + (L&3)*2
// uint4 = { {A[r,k0],A[r,k0+1]}, {A[r+8,k0],A[r+8,k0+1]},
//           {A[r,k0+8],A[r,k0+9]}, {A[r+8,k0+8],A[r+8,k0+9]} }
// ---------------------------------------------------------------------------
__global__ void convert_Afrag(const float* __restrict__ src, uint4* dst) {
    int t = blockIdx.x * 256 + threadIdx.x;     // 0..4194303
    int lane = t & 31, kstep = (t >> 5) & 31, mb = t >> 10;
    int r  = mb * 16 + (lane >> 2);
    int k0 = kstep * 16 + (lane & 3) * 2;
    const float* p = src + (size_t)r * D_ + k0;
    float2 f0 = *reinterpret_cast<const float2*>(p);
    float2 f1 = *reinterpret_cast<const float2*>(p + 8 * D_);
    float2 f2 = *reinterpret_cast<const float2*>(p + 8);
    float2 f3 = *reinterpret_cast<const float2*>(p + 8 * D_ + 8);
    dst[t] = make_uint4(pack_h2(f0.x, f0.y), pack_h2(f1.x, f1.y),
                        pack_h2(f2.x, f2.y), pack_h2(f3.x, f3.y));
}

// ---------------------------------------------------------------------------
// proj_frag: CTA 128m x 128n, 4 warps (2x2), warp tile 64x64.
// Mainloop: direct LDG of A/W fragments, cnt scaling via f16x2 mul, MMAs.
// Epilogue: out_f32 = in_f32 + scale*acc; also emits fp16 A fragments
// for the next iteration (identical lane layout, free repack).
// ---------------------------------------------------------------------------
__global__ __launch_bounds__(128, 2)
void proj_frag(const float* __restrict__ Ain, const uint4* __restrict__ AfIn,
               float* __restrict__ Cout, uint4* __restrict__ AfOut,
               float scale, int writeFrag)
{
    const int tid  = threadIdx.x;
    const int warp = tid >> 5, lane = tid & 31;
    const int n0   = blockIdx.x * 128;
    const int m0   = blockIdx.y * 128;
    const int wm   = (warp >> 1) * 64;
    const int wn   = (warp & 1) * 64;
    const int nbg0 = blockIdx.x * 16 + (warp & 1) * 8;
    const int mblkb = (m0 >> 4) + (warp >> 1) * 4;   // + mi

    float acc[4][8][4];
    #pragma unroll
    for (int mi = 0; mi < 4; ++mi)
        #pragma unroll
        for (int nb = 0; nb < 8; ++nb)
            #pragma unroll
            for (int q = 0; q < 4; ++q) acc[mi][nb][q] = 0.f;

    // per-warp fragment base offsets
    size_t aBase[4];
    #pragma unroll
    for (int mi = 0; mi < 4; ++mi)
        aBase[mi] = ((size_t)(mblkb + mi) * KSTEP) * 32 + lane;

    uint32_t c0[4], c1[4];     // cnt as packed half2, per mi (rows r / r+8)
    uint4 acur[4];
    uint2 bcur[8];

    // prefetch ss = 0 (ib=0, s=0) + cnt for ib=0
    #pragma unroll
    for (int mi = 0; mi < 4; ++mi) {
        int r = (m0 + wm + mi * 16 + (lane >> 2)) & (N_ - 1);
        float f0 = (float)__ldg(&g_cnt[r]);
        float f1 = (float)__ldg(&g_cnt[r + 8]);
        c0[mi] = pack_h2(f0, f0);
        c1[mi] = pack_h2(f1, f1);
        acur[mi] = __ldg(&AfIn[aBase[mi]]);
    }
    #pragma unroll
    for (int nb = 0; nb < 8; ++nb)
        bcur[nb] = __ldg(&g_Wfrag2[(size_t)(nbg0 + nb) * 32 + lane]);

    // flat loop over 128 k-steps (4 i-blocks x 32 steps)
    #pragma unroll 4
    for (int ss = 0; ss < 128; ++ss) {
        const int s_in = ss & 31;          // kstep within D
        uint4 anxt[4];
        uint2 bnxt[8];
        if (ss < 127) {
            const int sn = (ss + 1) & 31;
            #pragma unroll
            for (int mi = 0; mi < 4; ++mi)
                anxt[mi] = __ldg(&AfIn[aBase[mi] + (size_t)sn * 32]);
            const uint2* wb = g_Wfrag2 + ((size_t)(ss + 1) * 64 + nbg0) * 32 + lane;
            #pragma unroll
            for (int nb = 0; nb < 8; ++nb)
                bnxt[nb] = __ldg(&wb[(size_t)nb * 32]);
        }
        (void)s_in;

        // cnt-scale A fragments (exact small-int multiplier)
        uint32_t ah[4][4];
        #pragma unroll
        for (int mi = 0; mi < 4; ++mi) {
            ah[mi][0] = hmul2(acur[mi].x, c0[mi]);
            ah[mi][1] = hmul2(acur[mi].y, c1[mi]);
            ah[mi][2] = hmul2(acur[mi].z, c0[mi]);
            ah[mi][3] = hmul2(acur[mi].w, c1[mi]);
        }
        #pragma unroll
        for (int nb = 0; nb < 8; ++nb)
            #pragma unroll
            for (int mi = 0; mi < 4; ++mi)
                mma16816(acc[mi][nb], ah[mi], bcur[nb].x, bcur[nb].y);

        // rotate prefetch; reload cnt at i-block boundary
        #pragma unroll
        for (int mi = 0; mi < 4; ++mi) acur[mi] = anxt[mi];
        #pragma unroll
        for (int nb = 0; nb < 8; ++nb) bcur[nb] = bnxt[nb];
        if ((ss & 31) == 31 && ss < 127) {
            const int ib = (ss + 1) >> 5;
            #pragma unroll
            for (int mi = 0; mi < 4; ++mi) {
                int r = (m0 + wm + mi * 16 + (lane >> 2)) & (N_ - 1);
                float f0 = (float)__ldg(&g_cnt[ib * N_ + r]);
                float f1 = (float)__ldg(&g_cnt[ib * N_ + r + 8]);
                c0[mi] = pack_h2(f0, f0);
                c1[mi] = pack_h2(f1, f1);
            }
        }
    }

    // ---- epilogue: out = in + scale*acc; emit next-iter A fragments ----
    #pragma unroll
    for (int mi = 0; mi < 4; ++mi) {
        int row = m0 + wm + mi * 16 + (lane >> 2);
        const float* inr = Ain + (size_t)row * D_;
        float* outr = Cout + (size_t)row * D_;
        #pragma unroll
        for (int q = 0; q < 4; ++q) {
            int col = n0 + wn + q * 16 + (lane & 3) * 2;
            float2 iA0 = *reinterpret_cast<const float2*>(inr + col);
            float2 iA1 = *reinterpret_cast<const float2*>(inr + 8 * D_ + col);
            float2 iB0 = *reinterpret_cast<const float2*>(inr + col + 8);
            float2 iB1 = *reinterpret_cast<const float2*>(inr + 8 * D_ + col + 8);
            float o00 = iA0.x + scale * acc[mi][2 * q][0];
            float o01 = iA0.y + scale * acc[mi][2 * q][1];
            float o02 = iA1.x + scale * acc[mi][2 * q][2];
            float o03 = iA1.y + scale * acc[mi][2 * q][3];
            float o10 = iB0.x + scale * acc[mi][2 * q + 1][0];
            float o11 = iB0.y + scale * acc[mi][2 * q + 1][1];
            float o12 = iB1.x + scale * acc[mi][2 * q + 1][2];
            float o13 = iB1.y + scale * acc[mi][2 * q + 1][3];
            *reinterpret_cast<float2*>(outr + col)          = make_float2(o00, o01);
            *reinterpret_cast<float2*>(outr + 8 * D_ + col) = make_float2(o02, o03);
            *reinterpret_cast<float2*>(outr + col + 8)          = make_float2(o10, o11);
            *reinterpret_cast<float2*>(outr + 8 * D_ + col + 8) = make_float2(o12, o13);
            if (writeFrag) {
                int kstep = (n0 >> 4) + (warp & 1) * 4 + q;
                AfOut[((size_t)(mblkb + mi) * KSTEP + kstep) * 32 + lane] =
                    make_uint4(pack_h2(o00, o01), pack_h2(o02, o03),
                               pack_h2(o10, o11), pack_h2(o12, o13));
            }
        }
    }
}

// ---------------------------------------------------------------------------
// kernel_launch
// ---------------------------------------------------------------------------
extern "C" void kernel_launch(void* const* d_in, const int* in_sizes, int n_in,
                              void* d_out, int out_size) {
    const float* x      = (const float*)d_in[0];
    const float* W      = (const float*)d_in[1];
    const int*   groups = (const int*)d_in[2];
    float*       out    = (float*)d_out;

    zero_cnt<<<(P_ * N_) / 256, 256>>>();
    count_groups<<<(P_ * N_) / 256, 256>>>(groups);
    convert_Wfrag<<<(P_ * KSTEP * 64 * 32) / 256, 256>>>(W);

    float *bufA, *bufB;
    uint4 *frag;
    cudaGetSymbolAddress((void**)&bufA, g_bufA);
    cudaGetSymbolAddress((void**)&bufB, g_bufB);
    cudaGetSymbolAddress((void**)&frag, g_Afrag);
    uint4* frag0 = frag;
    uint4* frag1 = frag + (size_t)MBLK * KSTEP * 32;

    convert_Afrag<<<(MBLK * KSTEP * 32) / 256, 256>>>(x, frag0);

    dim3 grid(4, 512);
    proj_frag<<<grid, 128>>>(x,    frag0, bufA, frag1, 1.0f,        1);
    proj_frag<<<grid, 128>>>(bufA, frag1, bufB, frag0, 0.5f,        1);
    proj_frag<<<grid, 128>>>(bufB, frag0, out,  frag1, 1.0f / 3.0f, 0);
}

// round 7
// speedup vs baseline: 8.5776x; 1.0183x over previous
#include <cuda_runtime.h>
#include <cuda_fp16.h>
#include <stdint.h>

// ---------------------------------------------------------------------------
// upd_{t+1} = upd_t + (1/(t+1)) * sum_i diag(cnt_i) upd_t W_i
// Dense GEMM per iteration: M=65536, N=512, K=2048 (4 stacked W blocks).
// All operands in mma-FRAGMENT layout in global memory:
//   - W : fp16 fragments (uint2/lane), built once                (2 MB)
//   - A : fp16 fragments (uint4/lane) of upd, UNscaled           (64 MB x2)
//         cnt_i folded in at runtime via mul.f16x2 (exact small int)
//   - A fragments for iter t+1 emitted by iter t's epilogue (fused).
// Loop order (s outer, i-block inner) => each A fragment is loaded ONCE and
// reused for all 4 i-blocks from registers (4x less A traffic than R6).
// No shared memory, no ldmatrix, no __syncthreads in the GEMM.
// ---------------------------------------------------------------------------

#define B_    8
#define N_    8192
#define D_    512
#define P_    4
#define MTOT  (B_ * N_)          // 65536
#define TOT   (B_ * N_ * D_)
#define MBLK  (MTOT / 16)        // 4096
#define KSTEP (D_ / 16)          // 32

// Device scratch
__device__ float g_bufA[TOT];                       // fp32 state ping
__device__ float g_bufB[TOT];                       // fp32 state pong
__device__ uint4 g_Afrag[2][(size_t)MBLK * KSTEP * 32];  // 2 x 64 MB
__device__ uint2 g_Wfrag2[P_ * KSTEP * 64 * 32];    // 2 MB
__device__ int   g_cnt[P_ * N_];

// ---------------------------------------------------------------------------
// helpers
// ---------------------------------------------------------------------------
__device__ __forceinline__ void mma16816(float c[4], const uint32_t a[4],
                                         uint32_t b0, uint32_t b1) {
    asm volatile(
        "mma.sync.aligned.m16n8k16.row.col.f32.f16.f16.f32 "
        "{%0,%1,%2,%3}, {%4,%5,%6,%7}, {%8,%9}, {%0,%1,%2,%3};"
        : "+f"(c[0]), "+f"(c[1]), "+f"(c[2]), "+f"(c[3])
        : "r"(a[0]), "r"(a[1]), "r"(a[2]), "r"(a[3]), "r"(b0), "r"(b1));
}

__device__ __forceinline__ uint32_t pack_h2(float a, float b) {
    __half2 h = __float22half2_rn(make_float2(a, b));  // a -> low halfword
    return *reinterpret_cast<uint32_t*>(&h);
}

__device__ __forceinline__ uint32_t hmul2(uint32_t a, uint32_t c) {
    uint32_t r;
    asm("mul.rn.f16x2 %0, %1, %2;" : "=r"(r) : "r"(a), "r"(c));
    return r;
}

// ---------------------------------------------------------------------------
// cnt histogram
// ---------------------------------------------------------------------------
__global__ void zero_cnt() { g_cnt[blockIdx.x * 256 + threadIdx.x] = 0; }
__global__ void count_groups(const int* __restrict__ groups) {
    int idx = blockIdx.x * 256 + threadIdx.x;   // P*G*GS = 32768
    atomicAdd(&g_cnt[(idx >> 13) * N_ + groups[idx]], 1);
}

// ---------------------------------------------------------------------------
// convert_Wfrag: W[i][k][n] fp32 -> per-lane mma B fragments (fp16).
// lane L: b0 = {B[k0,n], B[k0+1,n]}, b1 = {B[k0+8,n], B[k0+9,n]},
// k0 = s*16 + (L&3)*2, n = nb*8 + (L>>2). Index = ((i*32+s)*64 + nb)*32 + L.
// ---------------------------------------------------------------------------
__global__ void convert_Wfrag(const float* __restrict__ W) {
    int t = blockIdx.x * 256 + threadIdx.x;     // 0..262143
    int lane = t & 31, nbg = (t >> 5) & 63, s = (t >> 11) & 31, i = t >> 16;
    int k0 = s * 16 + (lane & 3) * 2;
    int n  = nbg * 8 + (lane >> 2);
    const float* Wp = W + (size_t)i * D_ * D_;
    uint2 b;
    b.x = pack_h2(Wp[(size_t)(k0    ) * D_ + n], Wp[(size_t)(k0 + 1) * D_ + n]);
    b.y = pack_h2(Wp[(size_t)(k0 + 8) * D_ + n], Wp[(size_t)(k0 + 9) * D_ + n]);
    g_Wfrag2[t] = b;
}

// ---------------------------------------------------------------------------
// convert_Afrag: fp32 matrix [MTOT x D] -> fp16 A fragments.
// lane L of (m_blk, kstep): r = m_blk*16 + (L>>2), k0 = kstep*16 + (L&3)*2
// ---------------------------------------------------------------------------
__global__ void convert_Afrag(const float* __restrict__ src, uint4* dst) {
    int t = blockIdx.x * 256 + threadIdx.x;     // 0..4194303
    int lane = t & 31, kstep = (t >> 5) & 31, mb = t >> 10;
    int r  = mb * 16 + (lane >> 2);
    int k0 = kstep * 16 + (lane & 3) * 2;
    const float* p = src + (size_t)r * D_ + k0;
    float2 f0 = *reinterpret_cast<const float2*>(p);
    float2 f1 = *reinterpret_cast<const float2*>(p + 8 * D_);
    float2 f2 = *reinterpret_cast<const float2*>(p + 8);
    float2 f3 = *reinterpret_cast<const float2*>(p + 8 * D_ + 8);
    dst[t] = make_uint4(pack_h2(f0.x, f0.y), pack_h2(f1.x, f1.y),
                        pack_h2(f2.x, f2.y), pack_h2(f3.x, f3.y));
}

// ---------------------------------------------------------------------------
// proj_frag: CTA 128m x 128n, 4 warps (2x2), warp tile 64x64.
// s-outer / i-block-inner loop: A fragment loaded once per s, reused 4x.
// ---------------------------------------------------------------------------
__global__ __launch_bounds__(128, 2)
void proj_frag(const float* __restrict__ Ain, const uint4* __restrict__ AfIn,
               float* __restrict__ Cout, uint4* __restrict__ AfOut,
               float scale, int writeFrag)
{
    const int tid  = threadIdx.x;
    const int warp = tid >> 5, lane = tid & 31;
    const int n0   = blockIdx.x * 128;
    const int m0   = blockIdx.y * 128;
    const int wm   = (warp >> 1) * 64;
    const int wn   = (warp & 1) * 64;
    const int nbg0 = blockIdx.x * 16 + (warp & 1) * 8;
    const int mblkb = (m0 >> 4) + (warp >> 1) * 4;   // + mi

    float acc[4][8][4];
    #pragma unroll
    for (int mi = 0; mi < 4; ++mi)
        #pragma unroll
        for (int nb = 0; nb < 8; ++nb)
            #pragma unroll
            for (int q = 0; q < 4; ++q) acc[mi][nb][q] = 0.f;

    // per-warp A fragment base offsets
    size_t aBase[4];
    #pragma unroll
    for (int mi = 0; mi < 4; ++mi)
        aBase[mi] = ((size_t)(mblkb + mi) * KSTEP) * 32 + lane;

    // cnt for all 4 i-blocks, packed half2 per (ib, mi): rows r and r+8
    uint32_t c0[4][4], c1[4][4];
    #pragma unroll
    for (int ib = 0; ib < 4; ++ib)
        #pragma unroll
        for (int mi = 0; mi < 4; ++mi) {
            int r = (m0 + wm + mi * 16 + (lane >> 2)) & (N_ - 1);
            float f0 = (float)__ldg(&g_cnt[ib * N_ + r]);
            float f1 = (float)__ldg(&g_cnt[ib * N_ + r + 8]);
            c0[ib][mi] = pack_h2(f0, f0);
            c1[ib][mi] = pack_h2(f1, f1);
        }

    uint4 acur[4], anxt[4];
    uint2 bcur[8];

    // prefetch s=0 A and (s=0, ib=0) B
    #pragma unroll
    for (int mi = 0; mi < 4; ++mi) acur[mi] = __ldg(&AfIn[aBase[mi]]);
    #pragma unroll
    for (int nb = 0; nb < 8; ++nb)
        bcur[nb] = __ldg(&g_Wfrag2[(size_t)(nbg0 + nb) * 32 + lane]);

    for (int s = 0; s < 32; ++s) {
        // prefetch A for next s (covered by 128 MMAs of latency)
        if (s < 31) {
            #pragma unroll
            for (int mi = 0; mi < 4; ++mi)
                anxt[mi] = __ldg(&AfIn[aBase[mi] + (size_t)(s + 1) * 32]);
        }
        #pragma unroll
        for (int ib = 0; ib < 4; ++ib) {
            // prefetch next B group: (s, ib+1) or (s+1, 0)
            uint2 bnxt[8];
            if (!(ib == 3 && s == 31)) {
                int ibn = (ib + 1) & 3;
                int sn  = (ib == 3) ? s + 1 : s;
                const uint2* wb = g_Wfrag2 +
                    ((size_t)(ibn * KSTEP + sn) * 64 + nbg0) * 32 + lane;
                #pragma unroll
                for (int nb = 0; nb < 8; ++nb)
                    bnxt[nb] = __ldg(&wb[(size_t)nb * 32]);
            }

            // cnt-scale the shared A fragments for this i-block
            uint32_t ah[4][4];
            #pragma unroll
            for (int mi = 0; mi < 4; ++mi) {
                ah[mi][0] = hmul2(acur[mi].x, c0[ib][mi]);
                ah[mi][1] = hmul2(acur[mi].y, c1[ib][mi]);
                ah[mi][2] = hmul2(acur[mi].z, c0[ib][mi]);
                ah[mi][3] = hmul2(acur[mi].w, c1[ib][mi]);
            }
            #pragma unroll
            for (int nb = 0; nb < 8; ++nb)
                #pragma unroll
                for (int mi = 0; mi < 4; ++mi)
                    mma16816(acc[mi][nb], ah[mi], bcur[nb].x, bcur[nb].y);

            #pragma unroll
            for (int nb = 0; nb < 8; ++nb) bcur[nb] = bnxt[nb];
        }
        #pragma unroll
        for (int mi = 0; mi < 4; ++mi) acur[mi] = anxt[mi];
    }

    // ---- epilogue: out = in + scale*acc; emit next-iter A fragments ----
    #pragma unroll
    for (int mi = 0; mi < 4; ++mi) {
        int row = m0 + wm + mi * 16 + (lane >> 2);
        const float* inr = Ain + (size_t)row * D_;
        float* outr = Cout + (size_t)row * D_;
        #pragma unroll
        for (int q = 0; q < 4; ++q) {
            int col = n0 + wn + q * 16 + (lane & 3) * 2;
            float2 iA0 = *reinterpret_cast<const float2*>(inr + col);
            float2 iA1 = *reinterpret_cast<const float2*>(inr + 8 * D_ + col);
            float2 iB0 = *reinterpret_cast<const float2*>(inr + col + 8);
            float2 iB1 = *reinterpret_cast<const float2*>(inr + 8 * D_ + col + 8);
            float o00 = iA0.x + scale * acc[mi][2 * q][0];
            float o01 = iA0.y + scale * acc[mi][2 * q][1];
            float o02 = iA1.x + scale * acc[mi][2 * q][2];
            float o03 = iA1.y + scale * acc[mi][2 * q][3];
            float o10 = iB0.x + scale * acc[mi][2 * q + 1][0];
            float o11 = iB0.y + scale * acc[mi][2 * q + 1][1];
            float o12 = iB1.x + scale * acc[mi][2 * q + 1][2];
            float o13 = iB1.y + scale * acc[mi][2 * q + 1][3];
            *reinterpret_cast<float2*>(outr + col)          = make_float2(o00, o01);
            *reinterpret_cast<float2*>(outr + 8 * D_ + col) = make_float2(o02, o03);
            *reinterpret_cast<float2*>(outr + col + 8)          = make_float2(o10, o11);
            *reinterpret_cast<float2*>(outr + 8 * D_ + col + 8) = make_float2(o12, o13);
            if (writeFrag) {
                int kstep = (n0 >> 4) + (warp & 1) * 4 + q;
                AfOut[((size_t)(mblkb + mi) * KSTEP + kstep) * 32 + lane] =
                    make_uint4(pack_h2(o00, o01), pack_h2(o02, o03),
                               pack_h2(o10, o11), pack_h2(o12, o13));
            }
        }
    }
}

// ---------------------------------------------------------------------------
// kernel_launch
// ---------------------------------------------------------------------------
extern "C" void kernel_launch(void* const* d_in, const int* in_sizes, int n_in,
                              void* d_out, int out_size) {
    const float* x      = (const float*)d_in[0];
    const float* W      = (const float*)d_in[1];
    const int*   groups = (const int*)d_in[2];
    float*       out    = (float*)d_out;

    zero_cnt<<<(P_ * N_) / 256, 256>>>();
    count_groups<<<(P_ * N_) / 256, 256>>>(groups);
    convert_Wfrag<<<(P_ * KSTEP * 64 * 32) / 256, 256>>>(W);

    float *bufA, *bufB;
    uint4 *frag;
    cudaGetSymbolAddress((void**)&bufA, g_bufA);
    cudaGetSymbolAddress((void**)&bufB, g_bufB);
    cudaGetSymbolAddress((void**)&frag, g_Afrag);
    uint4* frag0 = frag;
    uint4* frag1 = frag + (size_t)MBLK * KSTEP * 32;

    convert_Afrag<<<(MBLK * KSTEP * 32) / 256, 256>>>(x, frag0);

    dim3 grid(4, 512);
    proj_frag<<<grid, 128>>>(x,    frag0, bufA, frag1, 1.0f,        1);
    proj_frag<<<grid, 128>>>(bufA, frag1, bufB, frag0, 0.5f,        1);
    proj_frag<<<grid, 128>>>(bufB, frag0, out,  frag1, 1.0f / 3.0f, 0);
}